// round 2
// baseline (speedup 1.0000x reference)
#include <cuda_runtime.h>
#include <math.h>

#define NNODES 50000
#define NEDGES 800000
#define FIN    500
#define FHID   128
#define FOUT   47

// ---- scratch (static device globals; no allocation allowed) ----
__device__ float g_dinv[NNODES];
__device__ float g_h1  [NNODES * FHID];   // (x@W1) * dinv[row]
__device__ float g_agg1[NNODES * FHID];
__device__ float g_z1  [NNODES * FHID];
__device__ float g_h2  [NNODES * FOUT];   // (z1@W2) * dinv[row]
__device__ float g_agg2[NNODES * FOUT];

// ---------------------------------------------------------------
// degree / dinv
// ---------------------------------------------------------------
__global__ void k_deg_init() {
    int i = blockIdx.x * blockDim.x + threadIdx.x;
    if (i < NNODES) g_dinv[i] = 1.0f;   // self-loop contributes 1
}

__global__ void k_deg_scatter(const int* __restrict__ ei) {
    int e = blockIdx.x * blockDim.x + threadIdx.x;
    if (e < NEDGES) atomicAdd(&g_dinv[ei[NEDGES + e]], 1.0f);
}

__global__ void k_dinv() {
    int i = blockIdx.x * blockDim.x + threadIdx.x;
    if (i < NNODES) g_dinv[i] = rsqrtf(g_dinv[i]);
}

// ---------------------------------------------------------------
// GEMM1: g_h1 = (x @ W1) * dinv[row];  g_agg1 = g_h1 (self-loop init)
// BM=128, BN=128, BK=8; 256 threads, 8x8 per thread
// ---------------------------------------------------------------
__global__ __launch_bounds__(256) void k_gemm1(const float* __restrict__ x,
                                               const float* __restrict__ W1) {
    __shared__ float sA[8][128];
    __shared__ float sB[8][128];
    const int tid  = threadIdx.x;
    const int row0 = blockIdx.x * 128;
    const int tx   = tid & 15;    // 16 col-groups of 8
    const int ty   = tid >> 4;    // 16 row-groups of 8

    const int arow = tid >> 1;         // 0..127
    const int ac4  = (tid & 1) * 4;    // 0 or 4 (k offset)
    const int brow = tid >> 5;         // 0..7   (k row)
    const int bc4  = (tid & 31) * 4;   // 0..124 (n offset)

    float acc[8][8];
#pragma unroll
    for (int m = 0; m < 8; m++)
#pragma unroll
        for (int n = 0; n < 8; n++) acc[m][n] = 0.0f;

    for (int k0 = 0; k0 < FIN; k0 += 8) {
        // load A tile (transposed into sA[k][row])
        float4 av = make_float4(0.f, 0.f, 0.f, 0.f);
        {
            int gr = row0 + arow;
            int gk = k0 + ac4;
            if (gr < NNODES && gk < FIN)
                av = *(const float4*)(x + (size_t)gr * FIN + gk);
        }
        sA[ac4 + 0][arow] = av.x;
        sA[ac4 + 1][arow] = av.y;
        sA[ac4 + 2][arow] = av.z;
        sA[ac4 + 3][arow] = av.w;
        // load B tile
        {
            int gk = k0 + brow;
            float4 bv = make_float4(0.f, 0.f, 0.f, 0.f);
            if (gk < FIN) bv = *(const float4*)(W1 + (size_t)gk * FHID + bc4);
            *(float4*)&sB[brow][bc4] = bv;
        }
        __syncthreads();
#pragma unroll
        for (int k = 0; k < 8; k++) {
            float a[8], b[8];
            *(float4*)(a)     = *(const float4*)&sA[k][ty * 8];
            *(float4*)(a + 4) = *(const float4*)&sA[k][ty * 8 + 4];
            *(float4*)(b)     = *(const float4*)&sB[k][tx * 8];
            *(float4*)(b + 4) = *(const float4*)&sB[k][tx * 8 + 4];
#pragma unroll
            for (int m = 0; m < 8; m++)
#pragma unroll
                for (int n = 0; n < 8; n++) acc[m][n] = fmaf(a[m], b[n], acc[m][n]);
        }
        __syncthreads();
    }

#pragma unroll
    for (int m = 0; m < 8; m++) {
        int r = row0 + ty * 8 + m;
        if (r >= NNODES) continue;
        float d = g_dinv[r];
        float4 v0, v1;
        v0.x = acc[m][0] * d; v0.y = acc[m][1] * d; v0.z = acc[m][2] * d; v0.w = acc[m][3] * d;
        v1.x = acc[m][4] * d; v1.y = acc[m][5] * d; v1.z = acc[m][6] * d; v1.w = acc[m][7] * d;
        size_t off = (size_t)r * FHID + tx * 8;
        *(float4*)(g_h1 + off)       = v0;
        *(float4*)(g_h1 + off + 4)   = v1;
        *(float4*)(g_agg1 + off)     = v0;
        *(float4*)(g_agg1 + off + 4) = v1;
    }
}

// ---------------------------------------------------------------
// scatter1: per edge, agg1[dst] += h1[src]  (128 floats, 1 warp/edge)
// ---------------------------------------------------------------
__global__ __launch_bounds__(256) void k_scatter1(const int* __restrict__ ei) {
    int w    = (blockIdx.x * blockDim.x + threadIdx.x) >> 5;
    int lane = threadIdx.x & 31;
    if (w >= NEDGES) return;
    int s = ei[w];
    int d = ei[NEDGES + w];
    float4 v = ((const float4*)(g_h1 + (size_t)s * FHID))[lane];
    float* dp = g_agg1 + (size_t)d * FHID + lane * 4;
    atomicAdd(dp + 0, v.x);
    atomicAdd(dp + 1, v.y);
    atomicAdd(dp + 2, v.z);
    atomicAdd(dp + 3, v.w);
}

// ---------------------------------------------------------------
// finish1: z1 = relu(dinv[i] * agg1 + b1)
// ---------------------------------------------------------------
__global__ __launch_bounds__(256) void k_finish1(const float* __restrict__ b1) {
    int idx = blockIdx.x * blockDim.x + threadIdx.x;   // float4 index
    if (idx >= NNODES * (FHID / 4)) return;
    int i  = idx >> 5;          // node
    int j4 = idx & 31;          // float4 within row
    float4 v = ((const float4*)g_agg1)[idx];
    float4 b = *(const float4*)(b1 + j4 * 4);
    float  d = g_dinv[i];
    float4 z;
    z.x = fmaxf(fmaf(d, v.x, b.x), 0.f);
    z.y = fmaxf(fmaf(d, v.y, b.y), 0.f);
    z.z = fmaxf(fmaf(d, v.z, b.z), 0.f);
    z.w = fmaxf(fmaf(d, v.w, b.w), 0.f);
    ((float4*)g_z1)[idx] = z;
}

// ---------------------------------------------------------------
// GEMM2: g_h2 = (z1 @ W2) * dinv[row]; g_agg2 = g_h2
// BM=128, N=47 (pad 48), K=128; 256 threads, 8x3 per thread
// ---------------------------------------------------------------
__global__ __launch_bounds__(256) void k_gemm2(const float* __restrict__ W2) {
    __shared__ float sA[16][128];
    __shared__ float sW[128][48];
    const int tid  = threadIdx.x;
    const int row0 = blockIdx.x * 128;
    const int tx   = tid & 15;   // 16 col-groups of 3
    const int ty   = tid >> 4;   // 16 row-groups of 8

    // load full W2 into smem (zero-pad col 47)
    for (int idx = tid; idx < 128 * 48; idx += 256) {
        int k = idx / 48, n = idx % 48;
        sW[k][n] = (n < FOUT) ? W2[k * FOUT + n] : 0.0f;
    }

    float acc[8][3];
#pragma unroll
    for (int m = 0; m < 8; m++)
#pragma unroll
        for (int n = 0; n < 3; n++) acc[m][n] = 0.0f;

    const int arow = tid >> 1;          // 0..127
    const int abase = (tid & 1) * 8;    // 0 or 8

    for (int k0 = 0; k0 < FHID; k0 += 16) {
        __syncthreads();
#pragma unroll
        for (int j = 0; j < 2; j++) {
            int c4 = abase + j * 4;
            float4 av = make_float4(0.f, 0.f, 0.f, 0.f);
            int gr = row0 + arow;
            if (gr < NNODES)
                av = *(const float4*)(g_z1 + (size_t)gr * FHID + k0 + c4);
            sA[c4 + 0][arow] = av.x;
            sA[c4 + 1][arow] = av.y;
            sA[c4 + 2][arow] = av.z;
            sA[c4 + 3][arow] = av.w;
        }
        __syncthreads();
#pragma unroll
        for (int k = 0; k < 16; k++) {
            float a[8];
            *(float4*)(a)     = *(const float4*)&sA[k][ty * 8];
            *(float4*)(a + 4) = *(const float4*)&sA[k][ty * 8 + 4];
            float b0 = sW[k0 + k][tx * 3 + 0];
            float b1 = sW[k0 + k][tx * 3 + 1];
            float b2 = sW[k0 + k][tx * 3 + 2];
#pragma unroll
            for (int m = 0; m < 8; m++) {
                acc[m][0] = fmaf(a[m], b0, acc[m][0]);
                acc[m][1] = fmaf(a[m], b1, acc[m][1]);
                acc[m][2] = fmaf(a[m], b2, acc[m][2]);
            }
        }
    }

#pragma unroll
    for (int m = 0; m < 8; m++) {
        int r = row0 + ty * 8 + m;
        if (r >= NNODES) continue;
        float d = g_dinv[r];
#pragma unroll
        for (int n = 0; n < 3; n++) {
            int c = tx * 3 + n;
            if (c < FOUT) {
                float v = acc[m][n] * d;
                size_t off = (size_t)r * FOUT + c;
                g_h2[off]   = v;
                g_agg2[off] = v;
            }
        }
    }
}

// ---------------------------------------------------------------
// scatter2: per edge, agg2[dst] += h2[src]  (47 floats, 1 warp/edge)
// ---------------------------------------------------------------
__global__ __launch_bounds__(256) void k_scatter2(const int* __restrict__ ei) {
    int w    = (blockIdx.x * blockDim.x + threadIdx.x) >> 5;
    int lane = threadIdx.x & 31;
    if (w >= NEDGES) return;
    int s = ei[w];
    int d = ei[NEDGES + w];
    const float* sr = g_h2 + (size_t)s * FOUT;
    float*       dr = g_agg2 + (size_t)d * FOUT;
    atomicAdd(dr + lane, sr[lane]);
    if (lane < FOUT - 32) atomicAdd(dr + 32 + lane, sr[32 + lane]);
}

// ---------------------------------------------------------------
// out: log_softmax(dinv[i]*agg2 + b2) per row, 1 warp/row
// ---------------------------------------------------------------
__global__ __launch_bounds__(256) void k_out(const float* __restrict__ b2,
                                             float* __restrict__ out) {
    int w    = (blockIdx.x * blockDim.x + threadIdx.x) >> 5;
    int lane = threadIdx.x & 31;
    if (w >= NNODES) return;
    float d = g_dinv[w];
    const float* row = g_agg2 + (size_t)w * FOUT;
    float v0 = fmaf(d, row[lane], b2[lane]);                       // lane < 32 < 47 always valid
    bool  has1 = (lane + 32) < FOUT;
    float v1 = has1 ? fmaf(d, row[lane + 32], b2[lane + 32]) : -INFINITY;
    float m = fmaxf(v0, v1);
#pragma unroll
    for (int o = 16; o; o >>= 1) m = fmaxf(m, __shfl_xor_sync(0xFFFFFFFFu, m, o));
    float s = expf(v0 - m) + (has1 ? expf(v1 - m) : 0.0f);
#pragma unroll
    for (int o = 16; o; o >>= 1) s += __shfl_xor_sync(0xFFFFFFFFu, s, o);
    float ls = m + logf(s);
    out[(size_t)w * FOUT + lane] = v0 - ls;
    if (has1) out[(size_t)w * FOUT + 32 + lane] = v1 - ls;
}

// ---------------------------------------------------------------
extern "C" void kernel_launch(void* const* d_in, const int* in_sizes, int n_in,
                              void* d_out, int out_size) {
    const float* x  = (const float*)d_in[0];
    const float* W1 = (const float*)d_in[1];
    const float* b1 = (const float*)d_in[2];
    const float* W2 = (const float*)d_in[3];
    const float* b2 = (const float*)d_in[4];
    const int*   ei = (const int*)d_in[5];     // int32: JAX x64-disabled downcasts int64
    float* out = (float*)d_out;

    (void)in_sizes; (void)n_in; (void)out_size;

    // degrees -> dinv
    k_deg_init   <<<(NNODES + 255) / 256, 256>>>();
    k_deg_scatter<<<(NEDGES + 255) / 256, 256>>>(ei);
    k_dinv       <<<(NNODES + 255) / 256, 256>>>();

    // layer 1
    k_gemm1   <<<(NNODES + 127) / 128, 256>>>(x, W1);
    k_scatter1<<<(NEDGES * 32 + 255) / 256, 256>>>(ei);
    k_finish1 <<<(NNODES * (FHID / 4) + 255) / 256, 256>>>(b1);

    // layer 2
    k_gemm2   <<<(NNODES + 127) / 128, 256>>>(W2);
    k_scatter2<<<(NEDGES * 32 + 255) / 256, 256>>>(ei);

    // log_softmax epilogue
    k_out<<<(NNODES * 32 + 255) / 256, 256>>>(b2, out);
}

// round 5
// speedup vs baseline: 2.0114x; 2.0114x over previous
#include <cuda_runtime.h>
#include <cuda_bf16.h>
#include <math.h>
#include <stdint.h>

#define NNODES 50000
#define NEDGES 800000
#define FIN    500
#define FHID   128
#define FOUT   47
#define F2S    48          // padded stride for layer-2 rows (16B-aligned)

// ---- scratch (static device globals; no allocation allowed) ----
__device__ float g_dinv[NNODES];
__device__ float g_h1  [NNODES * FHID];   // (x@W1) * dinv[row]
__device__ float g_agg1[NNODES * FHID];
__device__ float g_z1  [NNODES * FHID];
__device__ float g_h2  [NNODES * F2S];    // (z1@W2) * dinv[row], padded
__device__ float g_agg2[NNODES * F2S];

// ---------------------------------------------------------------
// degree / dinv
// ---------------------------------------------------------------
__global__ void k_deg_init() {
    int i = blockIdx.x * blockDim.x + threadIdx.x;
    if (i < NNODES) g_dinv[i] = 1.0f;   // self-loop contributes 1
}
__global__ void k_deg_scatter(const int* __restrict__ ei) {
    int e = blockIdx.x * blockDim.x + threadIdx.x;
    if (e < NEDGES) atomicAdd(&g_dinv[ei[NEDGES + e]], 1.0f);
}
__global__ void k_dinv() {
    int i = blockIdx.x * blockDim.x + threadIdx.x;
    if (i < NNODES) g_dinv[i] = rsqrtf(g_dinv[i]);
}

// ---------------------------------------------------------------
// helpers
// ---------------------------------------------------------------
__device__ __forceinline__ uint32_t smem_u32(const void* p) {
    return (uint32_t)__cvta_generic_to_shared(p);
}
__device__ __forceinline__ uint32_t pack_bf2(__nv_bfloat16 a, __nv_bfloat16 b) {
    // low half = a (lower address / even k), high half = b
    return (uint32_t)__bfloat16_as_ushort(a) | ((uint32_t)__bfloat16_as_ushort(b) << 16);
}

#define MMA_BF16(C, A, B)                                                     \
    asm volatile("mma.sync.aligned.m16n8k16.row.col.f32.bf16.bf16.f32 "       \
                 "{%0,%1,%2,%3}, {%4,%5,%6,%7}, {%8,%9}, {%0,%1,%2,%3};"      \
                 : "+f"((C)[0]), "+f"((C)[1]), "+f"((C)[2]), "+f"((C)[3])     \
                 : "r"((A)[0]), "r"((A)[1]), "r"((A)[2]), "r"((A)[3]),        \
                   "r"((B)[0]), "r"((B)[1]))

#define LDSM_X4(R, ADDR)                                                      \
    asm volatile("ldmatrix.sync.aligned.m8n8.x4.shared.b16 {%0,%1,%2,%3}, [%4];" \
                 : "=r"((R)[0]), "=r"((R)[1]), "=r"((R)[2]), "=r"((R)[3])     \
                 : "r"(ADDR))

#define LDSM_X2(R, ADDR)                                                      \
    asm volatile("ldmatrix.sync.aligned.m8n8.x2.shared.b16 {%0,%1}, [%2];"    \
                 : "=r"((R)[0]), "=r"((R)[1])                                 \
                 : "r"(ADDR))

// ---------------------------------------------------------------
// GEMM1 (tensor cores, bf16 2-term split, fp32 accum):
//   g_h1 = (x @ W1) * dinv[row];  g_agg1 = g_h1 (self-loop init)
// BM=128, BN=128 (full), BK=32; 256 threads = 8 warps (4m x 2n),
// each warp computes 32x64 via m16n8k16 frags.
// ---------------------------------------------------------------
#define SAS 40   // smem row stride (elements) for A (conflict-free ldmatrix)
#define SBS 40   // smem row stride for B (n-major)

__global__ __launch_bounds__(256) void k_gemm1(const float* __restrict__ x,
                                               const float* __restrict__ W1) {
    __shared__ __nv_bfloat16 sAhi[128 * SAS];
    __shared__ __nv_bfloat16 sAlo[128 * SAS];
    __shared__ __nv_bfloat16 sBhi[128 * SBS];
    __shared__ __nv_bfloat16 sBlo[128 * SBS];

    const int tid  = threadIdx.x;
    const int lane = tid & 31;
    const int wid  = tid >> 5;
    const int wm   = wid >> 1;      // 0..3
    const int wn   = wid & 1;       // 0..1
    const int row0 = blockIdx.x * 128;

    float c[2][8][4];
#pragma unroll
    for (int mt = 0; mt < 2; mt++)
#pragma unroll
        for (int nt = 0; nt < 8; nt++)
#pragma unroll
            for (int j = 0; j < 4; j++) c[mt][nt][j] = 0.0f;

    for (int it = 0; it < 16; ++it) {       // 16 * 32 = 512 >= 500 (tail zero-padded)
        const int k0 = it * 32;

        // ---- stage A tile (128 x 32 f32 -> bf16 hi/lo, m-major) ----
#pragma unroll
        for (int i = 0; i < 4; i++) {
            int fidx = tid + i * 256;       // 0..1023
            int r  = fidx >> 3;             // 0..127
            int kq = fidx & 7;              // float4 slot
            int gr = row0 + r;
            int gk = k0 + kq * 4;
            float4 v = make_float4(0.f, 0.f, 0.f, 0.f);
            if (gr < NNODES && gk + 3 < FIN)
                v = *(const float4*)(x + (size_t)gr * FIN + gk);
            __nv_bfloat16 h0 = __float2bfloat16_rn(v.x);
            __nv_bfloat16 h1 = __float2bfloat16_rn(v.y);
            __nv_bfloat16 h2 = __float2bfloat16_rn(v.z);
            __nv_bfloat16 h3 = __float2bfloat16_rn(v.w);
            __nv_bfloat16 l0 = __float2bfloat16_rn(v.x - __bfloat162float(h0));
            __nv_bfloat16 l1 = __float2bfloat16_rn(v.y - __bfloat162float(h1));
            __nv_bfloat16 l2 = __float2bfloat16_rn(v.z - __bfloat162float(h2));
            __nv_bfloat16 l3 = __float2bfloat16_rn(v.w - __bfloat162float(h3));
            int base = r * SAS + kq * 4;
            *(uint32_t*)&sAhi[base]     = pack_bf2(h0, h1);
            *(uint32_t*)&sAhi[base + 2] = pack_bf2(h2, h3);
            *(uint32_t*)&sAlo[base]     = pack_bf2(l0, l1);
            *(uint32_t*)&sAlo[base + 2] = pack_bf2(l2, l3);
        }

        // ---- stage B tile (32 x 128 f32 -> bf16 hi/lo, transposed to n-major) ----
#pragma unroll
        for (int i = 0; i < 4; i++) {
            int fidx = tid + i * 256;       // 0..1023
            int n  = fidx & 127;
            int kb = (fidx >> 7) * 4;       // 0,4,...,28
            float v[4];
#pragma unroll
            for (int j = 0; j < 4; j++) {
                int gk = k0 + kb + j;
                v[j] = (gk < FIN) ? W1[gk * FHID + n] : 0.0f;
            }
            __nv_bfloat16 h[4], l[4];
#pragma unroll
            for (int j = 0; j < 4; j++) {
                h[j] = __float2bfloat16_rn(v[j]);
                l[j] = __float2bfloat16_rn(v[j] - __bfloat162float(h[j]));
            }
            int base = n * SBS + kb;
            *(uint32_t*)&sBhi[base]     = pack_bf2(h[0], h[1]);
            *(uint32_t*)&sBhi[base + 2] = pack_bf2(h[2], h[3]);
            *(uint32_t*)&sBlo[base]     = pack_bf2(l[0], l[1]);
            *(uint32_t*)&sBlo[base + 2] = pack_bf2(l[2], l[3]);
        }
        __syncthreads();

        // ---- compute ----
#pragma unroll
        for (int kk = 0; kk < 32; kk += 16) {
            uint32_t ahi[2][4], alo[2][4];
#pragma unroll
            for (int mt = 0; mt < 2; mt++) {
                int r  = wm * 32 + mt * 16 + (lane & 15);
                int kc = kk + (lane >> 4) * 8;
                LDSM_X4(ahi[mt], smem_u32(&sAhi[r * SAS + kc]));
                LDSM_X4(alo[mt], smem_u32(&sAlo[r * SAS + kc]));
            }
#pragma unroll
            for (int nt = 0; nt < 8; nt++) {
                int bn = wn * 64 + nt * 8 + (lane & 7);
                int kc = kk + ((lane >> 3) & 1) * 8;
                uint32_t bh[2], bl[2];
                LDSM_X2(bh, smem_u32(&sBhi[bn * SBS + kc]));
                LDSM_X2(bl, smem_u32(&sBlo[bn * SBS + kc]));
#pragma unroll
                for (int mt = 0; mt < 2; mt++) {
                    MMA_BF16(c[mt][nt], ahi[mt], bh);   // hi*hi
                    MMA_BF16(c[mt][nt], ahi[mt], bl);   // hi*lo
                    MMA_BF16(c[mt][nt], alo[mt], bh);   // lo*hi
                }
            }
        }
        __syncthreads();
    }

    // ---- epilogue: scale by dinv, write h1 and agg1 ----
#pragma unroll
    for (int mt = 0; mt < 2; mt++) {
        int rA = row0 + wm * 32 + mt * 16 + (lane >> 2);
        int rB = rA + 8;
        float dA = (rA < NNODES) ? g_dinv[rA] : 0.f;
        float dB = (rB < NNODES) ? g_dinv[rB] : 0.f;
#pragma unroll
        for (int nt = 0; nt < 8; nt++) {
            int col = wn * 64 + nt * 8 + (lane & 3) * 2;
            if (rA < NNODES) {
                float2 v = make_float2(c[mt][nt][0] * dA, c[mt][nt][1] * dA);
                *(float2*)(g_h1   + (size_t)rA * FHID + col) = v;
                *(float2*)(g_agg1 + (size_t)rA * FHID + col) = v;
            }
            if (rB < NNODES) {
                float2 v = make_float2(c[mt][nt][2] * dB, c[mt][nt][3] * dB);
                *(float2*)(g_h1   + (size_t)rB * FHID + col) = v;
                *(float2*)(g_agg1 + (size_t)rB * FHID + col) = v;
            }
        }
    }
}

// ---------------------------------------------------------------
// scatter1: per edge, agg1[dst] += h1[src]  (128 floats, 1 warp/edge)
// vectorized red.global.add.v4.f32 (sm_90+)
// ---------------------------------------------------------------
__global__ __launch_bounds__(256) void k_scatter1(const int* __restrict__ ei) {
    int w    = (blockIdx.x * blockDim.x + threadIdx.x) >> 5;
    int lane = threadIdx.x & 31;
    if (w >= NEDGES) return;
    int s = ei[w];
    int d = ei[NEDGES + w];
    float4 v = ((const float4*)(g_h1 + (size_t)s * FHID))[lane];
    float* dp = g_agg1 + (size_t)d * FHID + lane * 4;
    asm volatile("red.global.add.v4.f32 [%0], {%1,%2,%3,%4};"
                 :: "l"(dp), "f"(v.x), "f"(v.y), "f"(v.z), "f"(v.w) : "memory");
}

// ---------------------------------------------------------------
// finish1: z1 = relu(dinv[i] * agg1 + b1)
// ---------------------------------------------------------------
__global__ __launch_bounds__(256) void k_finish1(const float* __restrict__ b1) {
    int idx = blockIdx.x * blockDim.x + threadIdx.x;   // float4 index
    if (idx >= NNODES * (FHID / 4)) return;
    int i  = idx >> 5;          // node
    int j4 = idx & 31;          // float4 within row
    float4 v = ((const float4*)g_agg1)[idx];
    float4 b = *(const float4*)(b1 + j4 * 4);
    float  d = g_dinv[i];
    float4 z;
    z.x = fmaxf(fmaf(d, v.x, b.x), 0.f);
    z.y = fmaxf(fmaf(d, v.y, b.y), 0.f);
    z.z = fmaxf(fmaf(d, v.z, b.z), 0.f);
    z.w = fmaxf(fmaf(d, v.w, b.w), 0.f);
    ((float4*)g_z1)[idx] = z;
}

// ---------------------------------------------------------------
// GEMM2: g_h2 = (z1 @ W2) * dinv[row]; g_agg2 = g_h2  (stride F2S=48)
// BM=128, N=48 (col 47 zero-padded via sW), K=128
// ---------------------------------------------------------------
__global__ __launch_bounds__(256) void k_gemm2(const float* __restrict__ W2) {
    __shared__ float sA[16][128];
    __shared__ float sW[128][48];
    const int tid  = threadIdx.x;
    const int row0 = blockIdx.x * 128;
    const int tx   = tid & 15;   // 16 col-groups of 3
    const int ty   = tid >> 4;   // 16 row-groups of 8

    for (int idx = tid; idx < 128 * 48; idx += 256) {
        int k = idx / 48, n = idx % 48;
        sW[k][n] = (n < FOUT) ? W2[k * FOUT + n] : 0.0f;
    }

    float acc[8][3];
#pragma unroll
    for (int m = 0; m < 8; m++)
#pragma unroll
        for (int n = 0; n < 3; n++) acc[m][n] = 0.0f;

    const int arow  = tid >> 1;
    const int abase = (tid & 1) * 8;

    for (int k0 = 0; k0 < FHID; k0 += 16) {
        __syncthreads();
#pragma unroll
        for (int j = 0; j < 2; j++) {
            int c4 = abase + j * 4;
            float4 av = make_float4(0.f, 0.f, 0.f, 0.f);
            int gr = row0 + arow;
            if (gr < NNODES)
                av = *(const float4*)(g_z1 + (size_t)gr * FHID + k0 + c4);
            sA[c4 + 0][arow] = av.x;
            sA[c4 + 1][arow] = av.y;
            sA[c4 + 2][arow] = av.z;
            sA[c4 + 3][arow] = av.w;
        }
        __syncthreads();
#pragma unroll
        for (int k = 0; k < 16; k++) {
            float a[8];
            *(float4*)(a)     = *(const float4*)&sA[k][ty * 8];
            *(float4*)(a + 4) = *(const float4*)&sA[k][ty * 8 + 4];
            float b0 = sW[k0 + k][tx * 3 + 0];
            float b1 = sW[k0 + k][tx * 3 + 1];
            float b2 = sW[k0 + k][tx * 3 + 2];
#pragma unroll
            for (int m = 0; m < 8; m++) {
                acc[m][0] = fmaf(a[m], b0, acc[m][0]);
                acc[m][1] = fmaf(a[m], b1, acc[m][1]);
                acc[m][2] = fmaf(a[m], b2, acc[m][2]);
            }
        }
    }

#pragma unroll
    for (int m = 0; m < 8; m++) {
        int r = row0 + ty * 8 + m;
        if (r >= NNODES) continue;
        float d = g_dinv[r];
#pragma unroll
        for (int n = 0; n < 3; n++) {
            int cidx = tx * 3 + n;          // 0..47 (col 47 is zero pad)
            float v = acc[m][n] * d;
            size_t off = (size_t)r * F2S + cidx;
            g_h2[off]   = v;
            g_agg2[off] = v;
        }
    }
}

// ---------------------------------------------------------------
// scatter2: per edge, agg2[dst] += h2[src] (48 padded floats, 2 edges/warp)
// ---------------------------------------------------------------
__global__ __launch_bounds__(256) void k_scatter2(const int* __restrict__ ei) {
    int gw   = (blockIdx.x * blockDim.x + threadIdx.x) >> 5;
    int lane = threadIdx.x & 31;
    int sub  = lane >> 4;       // 0/1 : which edge of the pair
    int li   = lane & 15;       // slot within edge
    int e = gw * 2 + sub;
    if (e >= NEDGES || li >= 12) return;    // 12 float4 = 48 floats
    int s = ei[e];
    int d = ei[NEDGES + e];
    float4 v = ((const float4*)(g_h2 + (size_t)s * F2S))[li];
    float* dp = g_agg2 + (size_t)d * F2S + li * 4;
    asm volatile("red.global.add.v4.f32 [%0], {%1,%2,%3,%4};"
                 :: "l"(dp), "f"(v.x), "f"(v.y), "f"(v.z), "f"(v.w) : "memory");
}

// ---------------------------------------------------------------
// out: log_softmax(dinv[i]*agg2 + b2) per row, 1 warp/row
// ---------------------------------------------------------------
__global__ __launch_bounds__(256) void k_out(const float* __restrict__ b2,
                                             float* __restrict__ out) {
    int w    = (blockIdx.x * blockDim.x + threadIdx.x) >> 5;
    int lane = threadIdx.x & 31;
    if (w >= NNODES) return;
    float d = g_dinv[w];
    const float* row = g_agg2 + (size_t)w * F2S;
    float v0 = fmaf(d, row[lane], b2[lane]);
    bool  has1 = (lane + 32) < FOUT;
    float v1 = has1 ? fmaf(d, row[lane + 32], b2[lane + 32]) : -INFINITY;
    float m = fmaxf(v0, v1);
#pragma unroll
    for (int o = 16; o; o >>= 1) m = fmaxf(m, __shfl_xor_sync(0xFFFFFFFFu, m, o));
    float s = expf(v0 - m) + (has1 ? expf(v1 - m) : 0.0f);
#pragma unroll
    for (int o = 16; o; o >>= 1) s += __shfl_xor_sync(0xFFFFFFFFu, s, o);
    float ls = m + logf(s);
    out[(size_t)w * FOUT + lane] = v0 - ls;
    if (has1) out[(size_t)w * FOUT + 32 + lane] = v1 - ls;
}

// ---------------------------------------------------------------
extern "C" void kernel_launch(void* const* d_in, const int* in_sizes, int n_in,
                              void* d_out, int out_size) {
    const float* x  = (const float*)d_in[0];
    const float* W1 = (const float*)d_in[1];
    const float* b1 = (const float*)d_in[2];
    const float* W2 = (const float*)d_in[3];
    const float* b2 = (const float*)d_in[4];
    const int*   ei = (const int*)d_in[5];     // int32 (JAX x64 disabled)
    float* out = (float*)d_out;

    (void)in_sizes; (void)n_in; (void)out_size;

    // degrees -> dinv
    k_deg_init   <<<(NNODES + 255) / 256, 256>>>();
    k_deg_scatter<<<(NEDGES + 255) / 256, 256>>>(ei);
    k_dinv       <<<(NNODES + 255) / 256, 256>>>();

    // layer 1
    k_gemm1   <<<(NNODES + 127) / 128, 256>>>(x, W1);
    k_scatter1<<<(NEDGES * 32 + 255) / 256, 256>>>(ei);
    k_finish1 <<<(NNODES * (FHID / 4) + 255) / 256, 256>>>(b1);

    // layer 2
    k_gemm2   <<<(NNODES + 127) / 128, 256>>>(W2);
    k_scatter2<<<((NEDGES / 2) * 32 + 255) / 256, 256>>>(ei);

    // log_softmax epilogue
    k_out<<<(NNODES * 32 + 255) / 256, 256>>>(b2, out);
}

// round 7
// speedup vs baseline: 2.1650x; 1.0764x over previous
#include <cuda_runtime.h>
#include <cuda_bf16.h>
#include <math.h>
#include <stdint.h>

#define NNODES 50000
#define NEDGES 800000
#define FIN    500
#define FHID   128
#define FOUT   47
#define F2S    48          // padded stride for layer-2 rows (16B-aligned)
#define KPAD   512         // padded K for W1 planes

// ---- scratch (static device globals; no allocation allowed) ----
__device__ float g_dinv[NNODES];
__device__ int   g_degi[NNODES];
__device__ int   g_off [NNODES + 1];
__device__ int   g_cur [NNODES];
__device__ int   g_csr [NEDGES];
__device__ float g_h1  [NNODES * FHID];   // (x@W1) * dinv[row]
__device__ float g_z1  [NNODES * FHID];
__device__ float g_h2  [NNODES * F2S];    // (z1@W2) * dinv[row], padded
__device__ __nv_bfloat16 g_w1hi[FHID * KPAD];   // n-major [128][512]
__device__ __nv_bfloat16 g_w1lo[FHID * KPAD];

// ---------------------------------------------------------------
// CSR build: count -> scan (+dinv) -> fill
// ---------------------------------------------------------------
__global__ void k_zero_deg() {
    int i = blockIdx.x * blockDim.x + threadIdx.x;
    if (i < NNODES) g_degi[i] = 0;
}
__global__ void k_count(const int* __restrict__ ei) {
    int e = blockIdx.x * blockDim.x + threadIdx.x;
    if (e < NEDGES) atomicAdd(&g_degi[ei[NEDGES + e]], 1);
}
__global__ __launch_bounds__(1024) void k_scan() {
    __shared__ int sdata[1024];
    const int t  = threadIdx.x;
    const int CH = (NNODES + 1023) / 1024;     // 49
    int lo = t * CH;
    int hi = lo + CH; if (hi > NNODES) hi = NNODES;
    int s = 0;
    for (int i = lo; i < hi; i++) s += g_degi[i];
    sdata[t] = s;
    __syncthreads();
    for (int o = 1; o < 1024; o <<= 1) {
        int v = (t >= o) ? sdata[t - o] : 0;
        __syncthreads();
        sdata[t] += v;
        __syncthreads();
    }
    int run = (t == 0) ? 0 : sdata[t - 1];
    for (int i = lo; i < hi; i++) {
        g_off[i] = run;
        g_cur[i] = run;
        g_dinv[i] = rsqrtf((float)(g_degi[i] + 1));   // +1 self-loop
        run += g_degi[i];
    }
    if (t == 1023) g_off[NNODES] = run;
}
__global__ void k_fill(const int* __restrict__ ei) {
    int e = blockIdx.x * blockDim.x + threadIdx.x;
    if (e >= NEDGES) return;
    int s = ei[e];
    int d = ei[NEDGES + e];
    int pos = atomicAdd(&g_cur[d], 1);
    g_csr[pos] = s;
}

// ---------------------------------------------------------------
// helpers
// ---------------------------------------------------------------
__device__ __forceinline__ uint32_t smem_u32(const void* p) {
    return (uint32_t)__cvta_generic_to_shared(p);
}
__device__ __forceinline__ uint32_t pack_bf2(__nv_bfloat16 a, __nv_bfloat16 b) {
    return (uint32_t)__bfloat16_as_ushort(a) | ((uint32_t)__bfloat16_as_ushort(b) << 16);
}

#define MMA_BF16(C, A, B)                                                     \
    asm volatile("mma.sync.aligned.m16n8k16.row.col.f32.bf16.bf16.f32 "       \
                 "{%0,%1,%2,%3}, {%4,%5,%6,%7}, {%8,%9}, {%0,%1,%2,%3};"      \
                 : "+f"((C)[0]), "+f"((C)[1]), "+f"((C)[2]), "+f"((C)[3])     \
                 : "r"((A)[0]), "r"((A)[1]), "r"((A)[2]), "r"((A)[3]),        \
                   "r"((B)[0]), "r"((B)[1]))

#define LDSM_X4(R, ADDR)                                                      \
    asm volatile("ldmatrix.sync.aligned.m8n8.x4.shared.b16 {%0,%1,%2,%3}, [%4];" \
                 : "=r"((R)[0]), "=r"((R)[1]), "=r"((R)[2]), "=r"((R)[3])     \
                 : "r"(ADDR))

#define LDSM_X2(R, ADDR)                                                      \
    asm volatile("ldmatrix.sync.aligned.m8n8.x2.shared.b16 {%0,%1}, [%2];"    \
                 : "=r"((R)[0]), "=r"((R)[1])                                 \
                 : "r"(ADDR))

// ---------------------------------------------------------------
// prep: W1 (500x128 f32, k-major) -> hi/lo bf16 planes, n-major [128][512]
// ---------------------------------------------------------------
__global__ void k_prep_w1(const float* __restrict__ W1) {
    int idx = blockIdx.x * blockDim.x + threadIdx.x;
    if (idx >= FHID * KPAD) return;
    int k = idx >> 7;        // 0..511 (coalesced read on W1 row)
    int n = idx & 127;
    float v = (k < FIN) ? W1[k * FHID + n] : 0.0f;
    __nv_bfloat16 h = __float2bfloat16_rn(v);
    __nv_bfloat16 l = __float2bfloat16_rn(v - __bfloat162float(h));
    g_w1hi[n * KPAD + k] = h;
    g_w1lo[n * KPAD + k] = l;
}

// ---------------------------------------------------------------
// GEMM1 (tensor cores, bf16 2-term split, fp32 accum, pipelined):
//   g_h1 = (x @ W1) * dinv[row]
// BM=128, BN=128, BK=32; 256 threads = 8 warps (4m x 2n)
// A: fp32 register-prefetch t+1 during compute of t; B: cp.async of
// precomputed bf16 planes.
// ---------------------------------------------------------------
#define SAS 40
#define SBS 40

__device__ __forceinline__ void loadA(const float* __restrict__ x, int row0,
                                      int tid, int k0, float4 v[4]) {
#pragma unroll
    for (int i = 0; i < 4; i++) {
        int fidx = tid + i * 256;
        int r  = fidx >> 3;
        int kq = fidx & 7;
        int gr = row0 + r;
        int gk = k0 + kq * 4;
        float4 t = make_float4(0.f, 0.f, 0.f, 0.f);
        if (gr < NNODES && gk + 3 < FIN)
            t = *(const float4*)(x + (size_t)gr * FIN + gk);
        v[i] = t;
    }
}

__global__ __launch_bounds__(256) void k_gemm1(const float* __restrict__ x) {
    __shared__ __nv_bfloat16 sAhi[128 * SAS];
    __shared__ __nv_bfloat16 sAlo[128 * SAS];
    __shared__ __nv_bfloat16 sBhi[128 * SBS];
    __shared__ __nv_bfloat16 sBlo[128 * SBS];

    const int tid  = threadIdx.x;
    const int lane = tid & 31;
    const int wid  = tid >> 5;
    const int wm   = wid >> 1;
    const int wn   = wid & 1;
    const int row0 = blockIdx.x * 128;

    float c[2][8][4];
#pragma unroll
    for (int mt = 0; mt < 2; mt++)
#pragma unroll
        for (int nt = 0; nt < 8; nt++)
#pragma unroll
            for (int j = 0; j < 4; j++) c[mt][nt][j] = 0.0f;

    float4 areg[4];
    loadA(x, row0, tid, 0, areg);

    for (int it = 0; it < 16; ++it) {
        const int k0 = it * 32;
        __syncthreads();          // previous compute done -> smem reusable

        // ---- store prefetched A (convert to hi/lo) ----
#pragma unroll
        for (int i = 0; i < 4; i++) {
            int fidx = tid + i * 256;
            int r  = fidx >> 3;
            int kq = fidx & 7;
            float4 v = areg[i];
            __nv_bfloat16 h0 = __float2bfloat16_rn(v.x);
            __nv_bfloat16 h1 = __float2bfloat16_rn(v.y);
            __nv_bfloat16 h2 = __float2bfloat16_rn(v.z);
            __nv_bfloat16 h3 = __float2bfloat16_rn(v.w);
            __nv_bfloat16 l0 = __float2bfloat16_rn(v.x - __bfloat162float(h0));
            __nv_bfloat16 l1 = __float2bfloat16_rn(v.y - __bfloat162float(h1));
            __nv_bfloat16 l2 = __float2bfloat16_rn(v.z - __bfloat162float(h2));
            __nv_bfloat16 l3 = __float2bfloat16_rn(v.w - __bfloat162float(h3));
            int base = r * SAS + kq * 4;
            *(uint32_t*)&sAhi[base]     = pack_bf2(h0, h1);
            *(uint32_t*)&sAhi[base + 2] = pack_bf2(h2, h3);
            *(uint32_t*)&sAlo[base]     = pack_bf2(l0, l1);
            *(uint32_t*)&sAlo[base + 2] = pack_bf2(l2, l3);
        }

        // ---- B tile via cp.async from precomputed planes ----
#pragma unroll
        for (int i = 0; i < 4; i++) {
            int fidx  = tid + i * 256;        // 0..1023
            int plane = fidx >> 9;            // 0=hi, 1=lo
            int rem   = fidx & 511;
            int n     = rem >> 2;
            int kq    = (rem & 3) * 8;        // 8 bf16 = 16B per copy
            const __nv_bfloat16* src =
                (plane ? g_w1lo : g_w1hi) + n * KPAD + k0 + kq;
            __nv_bfloat16* dst = (plane ? sBlo : sBhi) + n * SBS + kq;
            asm volatile("cp.async.cg.shared.global [%0], [%1], 16;"
                         :: "r"(smem_u32(dst)), "l"(src));
        }
        asm volatile("cp.async.commit_group;");

        // ---- prefetch next A tile into regs (overlaps with wait+compute) ----
        if (it + 1 < 16) loadA(x, row0, tid, (it + 1) * 32, areg);

        asm volatile("cp.async.wait_group 0;");
        __syncthreads();

        // ---- compute ----
#pragma unroll
        for (int kk = 0; kk < 32; kk += 16) {
            uint32_t ahi[2][4], alo[2][4];
#pragma unroll
            for (int mt = 0; mt < 2; mt++) {
                int r  = wm * 32 + mt * 16 + (lane & 15);
                int kc = kk + (lane >> 4) * 8;
                LDSM_X4(ahi[mt], smem_u32(&sAhi[r * SAS + kc]));
                LDSM_X4(alo[mt], smem_u32(&sAlo[r * SAS + kc]));
            }
#pragma unroll
            for (int nt = 0; nt < 8; nt++) {
                int bn = wn * 64 + nt * 8 + (lane & 7);
                int kc = kk + ((lane >> 3) & 1) * 8;
                uint32_t bh[2], bl[2];
                LDSM_X2(bh, smem_u32(&sBhi[bn * SBS + kc]));
                LDSM_X2(bl, smem_u32(&sBlo[bn * SBS + kc]));
#pragma unroll
                for (int mt = 0; mt < 2; mt++) {
                    MMA_BF16(c[mt][nt], ahi[mt], bh);   // hi*hi
                    MMA_BF16(c[mt][nt], ahi[mt], bl);   // hi*lo
                    MMA_BF16(c[mt][nt], alo[mt], bh);   // lo*hi
                }
            }
        }
    }

    // ---- epilogue: scale by dinv, write h1 ----
#pragma unroll
    for (int mt = 0; mt < 2; mt++) {
        int rA = row0 + wm * 32 + mt * 16 + (lane >> 2);
        int rB = rA + 8;
        float dA = (rA < NNODES) ? g_dinv[rA] : 0.f;
        float dB = (rB < NNODES) ? g_dinv[rB] : 0.f;
#pragma unroll
        for (int nt = 0; nt < 8; nt++) {
            int col = wn * 64 + nt * 8 + (lane & 3) * 2;
            if (rA < NNODES) {
                float2 v = make_float2(c[mt][nt][0] * dA, c[mt][nt][1] * dA);
                *(float2*)(g_h1 + (size_t)rA * FHID + col) = v;
            }
            if (rB < NNODES) {
                float2 v = make_float2(c[mt][nt][2] * dB, c[mt][nt][3] * dB);
                *(float2*)(g_h1 + (size_t)rB * FHID + col) = v;
            }
        }
    }
}

// ---------------------------------------------------------------
// agg1: one warp per dst node. acc = h1[dst] + sum_{src} h1[src];
//       z1 = relu(dinv*acc + b1). No atomics.
// ---------------------------------------------------------------
__global__ __launch_bounds__(256) void k_agg1(const float* __restrict__ b1) {
    int w    = (blockIdx.x * blockDim.x + threadIdx.x) >> 5;
    int lane = threadIdx.x & 31;
    if (w >= NNODES) return;
    const float4* base = (const float4*)g_h1;
    float4 acc = base[(size_t)w * 32 + lane];         // self-loop
    int p = g_off[w], e = g_off[w + 1];
    for (int p0 = p; p0 < e; p0 += 32) {
        int rem = e - p0;
        int s = (lane < rem) ? g_csr[p0 + lane] : 0;
        int cnt = rem < 32 ? rem : 32;
        for (int j = 0; j < cnt; j++) {
            int sj = __shfl_sync(0xFFFFFFFFu, s, j);
            float4 v = base[(size_t)sj * 32 + lane];
            acc.x += v.x; acc.y += v.y; acc.z += v.z; acc.w += v.w;
        }
    }
    float  d = g_dinv[w];
    float4 b = ((const float4*)b1)[lane];
    float4 z;
    z.x = fmaxf(fmaf(d, acc.x, b.x), 0.f);
    z.y = fmaxf(fmaf(d, acc.y, b.y), 0.f);
    z.z = fmaxf(fmaf(d, acc.z, b.z), 0.f);
    z.w = fmaxf(fmaf(d, acc.w, b.w), 0.f);
    ((float4*)g_z1)[(size_t)w * 32 + lane] = z;
}

// ---------------------------------------------------------------
// GEMM2: g_h2 = (z1 @ W2) * dinv[row]   (stride F2S=48, col 47 zero)
// ---------------------------------------------------------------
__global__ __launch_bounds__(256) void k_gemm2(const float* __restrict__ W2) {
    __shared__ float sA[16][128];
    __shared__ float sW[128][48];
    const int tid  = threadIdx.x;
    const int row0 = blockIdx.x * 128;
    const int tx   = tid & 15;
    const int ty   = tid >> 4;

    for (int idx = tid; idx < 128 * 48; idx += 256) {
        int k = idx / 48, n = idx % 48;
        sW[k][n] = (n < FOUT) ? W2[k * FOUT + n] : 0.0f;
    }

    float acc[8][3];
#pragma unroll
    for (int m = 0; m < 8; m++)
#pragma unroll
        for (int n = 0; n < 3; n++) acc[m][n] = 0.0f;

    const int arow  = tid >> 1;
    const int abase = (tid & 1) * 8;

    for (int k0 = 0; k0 < FHID; k0 += 16) {
        __syncthreads();
#pragma unroll
        for (int j = 0; j < 2; j++) {
            int c4 = abase + j * 4;
            float4 av = make_float4(0.f, 0.f, 0.f, 0.f);
            int gr = row0 + arow;
            if (gr < NNODES)
                av = *(const float4*)(g_z1 + (size_t)gr * FHID + k0 + c4);
            sA[c4 + 0][arow] = av.x;
            sA[c4 + 1][arow] = av.y;
            sA[c4 + 2][arow] = av.z;
            sA[c4 + 3][arow] = av.w;
        }
        __syncthreads();
#pragma unroll
        for (int k = 0; k < 16; k++) {
            float a[8];
            *(float4*)(a)     = *(const float4*)&sA[k][ty * 8];
            *(float4*)(a + 4) = *(const float4*)&sA[k][ty * 8 + 4];
            float b0 = sW[k0 + k][tx * 3 + 0];
            float b1 = sW[k0 + k][tx * 3 + 1];
            float b2 = sW[k0 + k][tx * 3 + 2];
#pragma unroll
            for (int m = 0; m < 8; m++) {
                acc[m][0] = fmaf(a[m], b0, acc[m][0]);
                acc[m][1] = fmaf(a[m], b1, acc[m][1]);
                acc[m][2] = fmaf(a[m], b2, acc[m][2]);
            }
        }
    }

#pragma unroll
    for (int m = 0; m < 8; m++) {
        int r = row0 + ty * 8 + m;
        if (r >= NNODES) continue;
        float d = g_dinv[r];
#pragma unroll
        for (int n = 0; n < 3; n++) {
            int cidx = tx * 3 + n;
            g_h2[(size_t)r * F2S + cidx] = acc[m][n] * d;
        }
    }
}

// ---------------------------------------------------------------
// agg2: one warp per dst. acc = h2[dst] + sum h2[src] (48 padded floats,
// lanes 0..11 hold float4 each); then fused bias + log_softmax -> out.
// ---------------------------------------------------------------
__global__ __launch_bounds__(256) void k_agg2(const float* __restrict__ b2,
                                              float* __restrict__ out) {
    int w    = (blockIdx.x * blockDim.x + threadIdx.x) >> 5;
    int lane = threadIdx.x & 31;
    if (w >= NNODES) return;
    const float4* base = (const float4*)g_h2;
    bool active = lane < 12;
    float4 acc = active ? base[(size_t)w * 12 + lane]
                        : make_float4(0.f, 0.f, 0.f, 0.f);
    int p = g_off[w], e = g_off[w + 1];
    for (int p0 = p; p0 < e; p0 += 32) {
        int rem = e - p0;
        int s = (lane < rem) ? g_csr[p0 + lane] : 0;
        int cnt = rem < 32 ? rem : 32;
        for (int j = 0; j < cnt; j++) {
            int sj = __shfl_sync(0xFFFFFFFFu, s, j);
            if (active) {
                float4 v = base[(size_t)sj * 12 + lane];
                acc.x += v.x; acc.y += v.y; acc.z += v.z; acc.w += v.w;
            }
        }
    }
    float d = g_dinv[w];
    float vv[4];
    float av[4] = {acc.x, acc.y, acc.z, acc.w};
    float m = -INFINITY;
#pragma unroll
    for (int j = 0; j < 4; j++) {
        int col = lane * 4 + j;
        vv[j] = (col < FOUT) ? fmaf(d, av[j], b2[col]) : -INFINITY;
        m = fmaxf(m, vv[j]);
    }
#pragma unroll
    for (int o = 16; o; o >>= 1) m = fmaxf(m, __shfl_xor_sync(0xFFFFFFFFu, m, o));
    float s = 0.f;
#pragma unroll
    for (int j = 0; j < 4; j++) {
        int col = lane * 4 + j;
        if (col < FOUT) s += expf(vv[j] - m);
    }
#pragma unroll
    for (int o = 16; o; o >>= 1) s += __shfl_xor_sync(0xFFFFFFFFu, s, o);
    float ls = m + logf(s);
#pragma unroll
    for (int j = 0; j < 4; j++) {
        int col = lane * 4 + j;
        if (col < FOUT) out[(size_t)w * FOUT + col] = vv[j] - ls;
    }
}

// ---------------------------------------------------------------
extern "C" void kernel_launch(void* const* d_in, const int* in_sizes, int n_in,
                              void* d_out, int out_size) {
    const float* x  = (const float*)d_in[0];
    const float* W1 = (const float*)d_in[1];
    const float* b1 = (const float*)d_in[2];
    const float* W2 = (const float*)d_in[3];
    const float* b2 = (const float*)d_in[4];
    const int*   ei = (const int*)d_in[5];     // int32 (JAX x64 disabled)
    float* out = (float*)d_out;

    (void)in_sizes; (void)n_in; (void)out_size;

    // CSR build + dinv
    k_zero_deg<<<(NNODES + 255) / 256, 256>>>();
    k_count   <<<(NEDGES + 255) / 256, 256>>>(ei);
    k_scan    <<<1, 1024>>>();
    k_fill    <<<(NEDGES + 255) / 256, 256>>>(ei);

    // W1 bf16 planes
    k_prep_w1<<<(FHID * KPAD + 255) / 256, 256>>>(W1);

    // layer 1
    k_gemm1<<<(NNODES + 127) / 128, 256>>>(x);
    k_agg1 <<<(NNODES * 32 + 255) / 256, 256>>>(b1);

    // layer 2
    k_gemm2<<<(NNODES + 127) / 128, 256>>>(W2);
    k_agg2 <<<(NNODES * 32 + 255) / 256, 256>>>(b2, out);
}

// round 8
// speedup vs baseline: 2.1679x; 1.0013x over previous
#include <cuda_runtime.h>
#include <cuda_bf16.h>
#include <math.h>
#include <stdint.h>

#define NNODES 50000
#define NEDGES 800000
#define FIN    500
#define FHID   128
#define FOUT   47
#define F2S    48          // padded stride for layer-2 rows (16B-aligned)
#define KPAD   512         // padded K for W1 planes

// ---- scratch (static device globals; no allocation allowed) ----
__device__ float g_dinv[NNODES];
__device__ int   g_degi[NNODES];
__device__ int   g_off [NNODES + 1];
__device__ int   g_cur [NNODES];
__device__ int   g_csr [NEDGES];
__device__ float g_h1  [NNODES * FHID];   // (x@W1) * dinv[row]
__device__ float g_z1  [NNODES * FHID];
__device__ float g_h2  [NNODES * F2S];    // (z1@W2) * dinv[row], padded
__device__ __nv_bfloat16 g_w1hi[FHID * KPAD];   // n-major [128][512]
__device__ __nv_bfloat16 g_w1lo[FHID * KPAD];

// ---------------------------------------------------------------
// CSR build: count -> scan (+dinv) -> fill
// ---------------------------------------------------------------
__global__ void k_zero_deg() {
    int i = blockIdx.x * blockDim.x + threadIdx.x;
    if (i < NNODES) g_degi[i] = 0;
}
__global__ void k_count(const int* __restrict__ ei) {
    int e = blockIdx.x * blockDim.x + threadIdx.x;
    if (e < NEDGES) atomicAdd(&g_degi[ei[NEDGES + e]], 1);
}
__global__ __launch_bounds__(1024) void k_scan() {
    __shared__ int sdata[1024];
    const int t  = threadIdx.x;
    const int CH = (NNODES + 1023) / 1024;     // 49
    int lo = t * CH;
    int hi = lo + CH; if (hi > NNODES) hi = NNODES;
    int s = 0;
    for (int i = lo; i < hi; i++) s += g_degi[i];
    sdata[t] = s;
    __syncthreads();
    for (int o = 1; o < 1024; o <<= 1) {
        int v = (t >= o) ? sdata[t - o] : 0;
        __syncthreads();
        sdata[t] += v;
        __syncthreads();
    }
    int run = (t == 0) ? 0 : sdata[t - 1];
    for (int i = lo; i < hi; i++) {
        g_off[i] = run;
        g_cur[i] = run;
        g_dinv[i] = rsqrtf((float)(g_degi[i] + 1));   // +1 self-loop
        run += g_degi[i];
    }
    if (t == 1023) g_off[NNODES] = run;
}
__global__ void k_fill(const int* __restrict__ ei) {
    int e = blockIdx.x * blockDim.x + threadIdx.x;
    if (e >= NEDGES) return;
    int s = ei[e];
    int d = ei[NEDGES + e];
    int pos = atomicAdd(&g_cur[d], 1);
    g_csr[pos] = s;
}

// ---------------------------------------------------------------
// helpers
// ---------------------------------------------------------------
__device__ __forceinline__ uint32_t smem_u32(const void* p) {
    return (uint32_t)__cvta_generic_to_shared(p);
}
__device__ __forceinline__ uint32_t pack_bf2(__nv_bfloat16 a, __nv_bfloat16 b) {
    return (uint32_t)__bfloat16_as_ushort(a) | ((uint32_t)__bfloat16_as_ushort(b) << 16);
}

#define MMA_BF16(C, A, B)                                                     \
    asm volatile("mma.sync.aligned.m16n8k16.row.col.f32.bf16.bf16.f32 "       \
                 "{%0,%1,%2,%3}, {%4,%5,%6,%7}, {%8,%9}, {%0,%1,%2,%3};"      \
                 : "+f"((C)[0]), "+f"((C)[1]), "+f"((C)[2]), "+f"((C)[3])     \
                 : "r"((A)[0]), "r"((A)[1]), "r"((A)[2]), "r"((A)[3]),        \
                   "r"((B)[0]), "r"((B)[1]))

#define LDSM_X4(R, ADDR)                                                      \
    asm volatile("ldmatrix.sync.aligned.m8n8.x4.shared.b16 {%0,%1,%2,%3}, [%4];" \
                 : "=r"((R)[0]), "=r"((R)[1]), "=r"((R)[2]), "=r"((R)[3])     \
                 : "r"(ADDR))

#define LDSM_X2(R, ADDR)                                                      \
    asm volatile("ldmatrix.sync.aligned.m8n8.x2.shared.b16 {%0,%1}, [%2];"    \
                 : "=r"((R)[0]), "=r"((R)[1])                                 \
                 : "r"(ADDR))

// ---------------------------------------------------------------
// prep: W1 (500x128 f32, k-major) -> hi/lo bf16 planes, n-major [128][512]
// ---------------------------------------------------------------
__global__ void k_prep_w1(const float* __restrict__ W1) {
    int idx = blockIdx.x * blockDim.x + threadIdx.x;
    if (idx >= FHID * KPAD) return;
    int k = idx >> 7;        // 0..511 (coalesced read on W1 row)
    int n = idx & 127;
    float v = (k < FIN) ? W1[k * FHID + n] : 0.0f;
    __nv_bfloat16 h = __float2bfloat16_rn(v);
    __nv_bfloat16 l = __float2bfloat16_rn(v - __bfloat162float(h));
    g_w1hi[n * KPAD + k] = h;
    g_w1lo[n * KPAD + k] = l;
}

// ---------------------------------------------------------------
// GEMM1 (tensor cores, bf16 2-term split, fp32 accum, pipelined):
//   g_h1 = (x @ W1) * dinv[row]
// BM=128, BN=128, BK=32; 256 threads = 8 warps (4m x 2n)
// A: fp32 register-prefetch t+1 during compute of t; B: cp.async of
// precomputed bf16 planes.
// ---------------------------------------------------------------
#define SAS 40
#define SBS 40

__device__ __forceinline__ void loadA(const float* __restrict__ x, int row0,
                                      int tid, int k0, float4 v[4]) {
#pragma unroll
    for (int i = 0; i < 4; i++) {
        int fidx = tid + i * 256;
        int r  = fidx >> 3;
        int kq = fidx & 7;
        int gr = row0 + r;
        int gk = k0 + kq * 4;
        float4 t = make_float4(0.f, 0.f, 0.f, 0.f);
        if (gr < NNODES && gk + 3 < FIN)
            t = *(const float4*)(x + (size_t)gr * FIN + gk);
        v[i] = t;
    }
}

__global__ __launch_bounds__(256) void k_gemm1(const float* __restrict__ x) {
    __shared__ __nv_bfloat16 sAhi[128 * SAS];
    __shared__ __nv_bfloat16 sAlo[128 * SAS];
    __shared__ __nv_bfloat16 sBhi[128 * SBS];
    __shared__ __nv_bfloat16 sBlo[128 * SBS];

    const int tid  = threadIdx.x;
    const int lane = tid & 31;
    const int wid  = tid >> 5;
    const int wm   = wid >> 1;
    const int wn   = wid & 1;
    const int row0 = blockIdx.x * 128;

    float c[2][8][4];
#pragma unroll
    for (int mt = 0; mt < 2; mt++)
#pragma unroll
        for (int nt = 0; nt < 8; nt++)
#pragma unroll
            for (int j = 0; j < 4; j++) c[mt][nt][j] = 0.0f;

    float4 areg[4];
    loadA(x, row0, tid, 0, areg);

    for (int it = 0; it < 16; ++it) {
        const int k0 = it * 32;
        __syncthreads();          // previous compute done -> smem reusable

        // ---- store prefetched A (convert to hi/lo) ----
#pragma unroll
        for (int i = 0; i < 4; i++) {
            int fidx = tid + i * 256;
            int r  = fidx >> 3;
            int kq = fidx & 7;
            float4 v = areg[i];
            __nv_bfloat16 h0 = __float2bfloat16_rn(v.x);
            __nv_bfloat16 h1 = __float2bfloat16_rn(v.y);
            __nv_bfloat16 h2 = __float2bfloat16_rn(v.z);
            __nv_bfloat16 h3 = __float2bfloat16_rn(v.w);
            __nv_bfloat16 l0 = __float2bfloat16_rn(v.x - __bfloat162float(h0));
            __nv_bfloat16 l1 = __float2bfloat16_rn(v.y - __bfloat162float(h1));
            __nv_bfloat16 l2 = __float2bfloat16_rn(v.z - __bfloat162float(h2));
            __nv_bfloat16 l3 = __float2bfloat16_rn(v.w - __bfloat162float(h3));
            int base = r * SAS + kq * 4;
            *(uint32_t*)&sAhi[base]     = pack_bf2(h0, h1);
            *(uint32_t*)&sAhi[base + 2] = pack_bf2(h2, h3);
            *(uint32_t*)&sAlo[base]     = pack_bf2(l0, l1);
            *(uint32_t*)&sAlo[base + 2] = pack_bf2(l2, l3);
        }

        // ---- B tile via cp.async from precomputed planes ----
#pragma unroll
        for (int i = 0; i < 4; i++) {
            int fidx  = tid + i * 256;        // 0..1023
            int plane = fidx >> 9;            // 0=hi, 1=lo
            int rem   = fidx & 511;
            int n     = rem >> 2;
            int kq    = (rem & 3) * 8;        // 8 bf16 = 16B per copy
            const __nv_bfloat16* src =
                (plane ? g_w1lo : g_w1hi) + n * KPAD + k0 + kq;
            __nv_bfloat16* dst = (plane ? sBlo : sBhi) + n * SBS + kq;
            asm volatile("cp.async.cg.shared.global [%0], [%1], 16;"
                         :: "r"(smem_u32(dst)), "l"(src));
        }
        asm volatile("cp.async.commit_group;");

        // ---- prefetch next A tile into regs (overlaps with wait+compute) ----
        if (it + 1 < 16) loadA(x, row0, tid, (it + 1) * 32, areg);

        asm volatile("cp.async.wait_group 0;");
        __syncthreads();

        // ---- compute ----
#pragma unroll
        for (int kk = 0; kk < 32; kk += 16) {
            uint32_t ahi[2][4], alo[2][4];
#pragma unroll
            for (int mt = 0; mt < 2; mt++) {
                int r  = wm * 32 + mt * 16 + (lane & 15);
                int kc = kk + (lane >> 4) * 8;
                LDSM_X4(ahi[mt], smem_u32(&sAhi[r * SAS + kc]));
                LDSM_X4(alo[mt], smem_u32(&sAlo[r * SAS + kc]));
            }
#pragma unroll
            for (int nt = 0; nt < 8; nt++) {
                int bn = wn * 64 + nt * 8 + (lane & 7);
                int kc = kk + ((lane >> 3) & 1) * 8;
                uint32_t bh[2], bl[2];
                LDSM_X2(bh, smem_u32(&sBhi[bn * SBS + kc]));
                LDSM_X2(bl, smem_u32(&sBlo[bn * SBS + kc]));
#pragma unroll
                for (int mt = 0; mt < 2; mt++) {
                    MMA_BF16(c[mt][nt], ahi[mt], bh);   // hi*hi
                    MMA_BF16(c[mt][nt], ahi[mt], bl);   // hi*lo
                    MMA_BF16(c[mt][nt], alo[mt], bh);   // lo*hi
                }
            }
        }
    }

    // ---- epilogue: scale by dinv, write h1 ----
#pragma unroll
    for (int mt = 0; mt < 2; mt++) {
        int rA = row0 + wm * 32 + mt * 16 + (lane >> 2);
        int rB = rA + 8;
        float dA = (rA < NNODES) ? g_dinv[rA] : 0.f;
        float dB = (rB < NNODES) ? g_dinv[rB] : 0.f;
#pragma unroll
        for (int nt = 0; nt < 8; nt++) {
            int col = wn * 64 + nt * 8 + (lane & 3) * 2;
            if (rA < NNODES) {
                float2 v = make_float2(c[mt][nt][0] * dA, c[mt][nt][1] * dA);
                *(float2*)(g_h1 + (size_t)rA * FHID + col) = v;
            }
            if (rB < NNODES) {
                float2 v = make_float2(c[mt][nt][2] * dB, c[mt][nt][3] * dB);
                *(float2*)(g_h1 + (size_t)rB * FHID + col) = v;
            }
        }
    }
}

// ---------------------------------------------------------------
// agg1: one warp per dst node. acc = h1[dst] + sum_{src} h1[src];
//       z1 = relu(dinv*acc + b1). No atomics.
// ---------------------------------------------------------------
__global__ __launch_bounds__(256) void k_agg1(const float* __restrict__ b1) {
    int w    = (blockIdx.x * blockDim.x + threadIdx.x) >> 5;
    int lane = threadIdx.x & 31;
    if (w >= NNODES) return;
    const float4* base = (const float4*)g_h1;
    float4 acc = base[(size_t)w * 32 + lane];         // self-loop
    int p = g_off[w], e = g_off[w + 1];
    for (int p0 = p; p0 < e; p0 += 32) {
        int rem = e - p0;
        int s = (lane < rem) ? g_csr[p0 + lane] : 0;
        int cnt = rem < 32 ? rem : 32;
        for (int j = 0; j < cnt; j++) {
            int sj = __shfl_sync(0xFFFFFFFFu, s, j);
            float4 v = base[(size_t)sj * 32 + lane];
            acc.x += v.x; acc.y += v.y; acc.z += v.z; acc.w += v.w;
        }
    }
    float  d = g_dinv[w];
    float4 b = ((const float4*)b1)[lane];
    float4 z;
    z.x = fmaxf(fmaf(d, acc.x, b.x), 0.f);
    z.y = fmaxf(fmaf(d, acc.y, b.y), 0.f);
    z.z = fmaxf(fmaf(d, acc.z, b.z), 0.f);
    z.w = fmaxf(fmaf(d, acc.w, b.w), 0.f);
    ((float4*)g_z1)[(size_t)w * 32 + lane] = z;
}

// ---------------------------------------------------------------
// GEMM2: g_h2 = (z1 @ W2) * dinv[row]   (stride F2S=48, col 47 zero)
// ---------------------------------------------------------------
__global__ __launch_bounds__(256) void k_gemm2(const float* __restrict__ W2) {
    __shared__ float sA[16][128];
    __shared__ float sW[128][48];
    const int tid  = threadIdx.x;
    const int row0 = blockIdx.x * 128;
    const int tx   = tid & 15;
    const int ty   = tid >> 4;

    for (int idx = tid; idx < 128 * 48; idx += 256) {
        int k = idx / 48, n = idx % 48;
        sW[k][n] = (n < FOUT) ? W2[k * FOUT + n] : 0.0f;
    }

    float acc[8][3];
#pragma unroll
    for (int m = 0; m < 8; m++)
#pragma unroll
        for (int n = 0; n < 3; n++) acc[m][n] = 0.0f;

    const int arow  = tid >> 1;
    const int abase = (tid & 1) * 8;

    for (int k0 = 0; k0 < FHID; k0 += 16) {
        __syncthreads();
#pragma unroll
        for (int j = 0; j < 2; j++) {
            int c4 = abase + j * 4;
            float4 av = make_float4(0.f, 0.f, 0.f, 0.f);
            int gr = row0 + arow;
            if (gr < NNODES)
                av = *(const float4*)(g_z1 + (size_t)gr * FHID + k0 + c4);
            sA[c4 + 0][arow] = av.x;
            sA[c4 + 1][arow] = av.y;
            sA[c4 + 2][arow] = av.z;
            sA[c4 + 3][arow] = av.w;
        }
        __syncthreads();
#pragma unroll
        for (int k = 0; k < 16; k++) {
            float a[8];
            *(float4*)(a)     = *(const float4*)&sA[k][ty * 8];
            *(float4*)(a + 4) = *(const float4*)&sA[k][ty * 8 + 4];
            float b0 = sW[k0 + k][tx * 3 + 0];
            float b1 = sW[k0 + k][tx * 3 + 1];
            float b2 = sW[k0 + k][tx * 3 + 2];
#pragma unroll
            for (int m = 0; m < 8; m++) {
                acc[m][0] = fmaf(a[m], b0, acc[m][0]);
                acc[m][1] = fmaf(a[m], b1, acc[m][1]);
                acc[m][2] = fmaf(a[m], b2, acc[m][2]);
            }
        }
    }

#pragma unroll
    for (int m = 0; m < 8; m++) {
        int r = row0 + ty * 8 + m;
        if (r >= NNODES) continue;
        float d = g_dinv[r];
#pragma unroll
        for (int n = 0; n < 3; n++) {
            int cidx = tx * 3 + n;
            g_h2[(size_t)r * F2S + cidx] = acc[m][n] * d;
        }
    }
}

// ---------------------------------------------------------------
// agg2: one warp per dst. acc = h2[dst] + sum h2[src] (48 padded floats,
// lanes 0..11 hold float4 each); then fused bias + log_softmax -> out.
// ---------------------------------------------------------------
__global__ __launch_bounds__(256) void k_agg2(const float* __restrict__ b2,
                                              float* __restrict__ out) {
    int w    = (blockIdx.x * blockDim.x + threadIdx.x) >> 5;
    int lane = threadIdx.x & 31;
    if (w >= NNODES) return;
    const float4* base = (const float4*)g_h2;
    bool active = lane < 12;
    float4 acc = active ? base[(size_t)w * 12 + lane]
                        : make_float4(0.f, 0.f, 0.f, 0.f);
    int p = g_off[w], e = g_off[w + 1];
    for (int p0 = p; p0 < e; p0 += 32) {
        int rem = e - p0;
        int s = (lane < rem) ? g_csr[p0 + lane] : 0;
        int cnt = rem < 32 ? rem : 32;
        for (int j = 0; j < cnt; j++) {
            int sj = __shfl_sync(0xFFFFFFFFu, s, j);
            if (active) {
                float4 v = base[(size_t)sj * 12 + lane];
                acc.x += v.x; acc.y += v.y; acc.z += v.z; acc.w += v.w;
            }
        }
    }
    float d = g_dinv[w];
    float vv[4];
    float av[4] = {acc.x, acc.y, acc.z, acc.w};
    float m = -INFINITY;
#pragma unroll
    for (int j = 0; j < 4; j++) {
        int col = lane * 4 + j;
        vv[j] = (col < FOUT) ? fmaf(d, av[j], b2[col]) : -INFINITY;
        m = fmaxf(m, vv[j]);
    }
#pragma unroll
    for (int o = 16; o; o >>= 1) m = fmaxf(m, __shfl_xor_sync(0xFFFFFFFFu, m, o));
    float s = 0.f;
#pragma unroll
    for (int j = 0; j < 4; j++) {
        int col = lane * 4 + j;
        if (col < FOUT) s += expf(vv[j] - m);
    }
#pragma unroll
    for (int o = 16; o; o >>= 1) s += __shfl_xor_sync(0xFFFFFFFFu, s, o);
    float ls = m + logf(s);
#pragma unroll
    for (int j = 0; j < 4; j++) {
        int col = lane * 4 + j;
        if (col < FOUT) out[(size_t)w * FOUT + col] = vv[j] - ls;
    }
}

// ---------------------------------------------------------------
extern "C" void kernel_launch(void* const* d_in, const int* in_sizes, int n_in,
                              void* d_out, int out_size) {
    const float* x  = (const float*)d_in[0];
    const float* W1 = (const float*)d_in[1];
    const float* b1 = (const float*)d_in[2];
    const float* W2 = (const float*)d_in[3];
    const float* b2 = (const float*)d_in[4];
    const int*   ei = (const int*)d_in[5];     // int32 (JAX x64 disabled)
    float* out = (float*)d_out;

    (void)in_sizes; (void)n_in; (void)out_size;

    // CSR build + dinv
    k_zero_deg<<<(NNODES + 255) / 256, 256>>>();
    k_count   <<<(NEDGES + 255) / 256, 256>>>(ei);
    k_scan    <<<1, 1024>>>();
    k_fill    <<<(NEDGES + 255) / 256, 256>>>(ei);

    // W1 bf16 planes
    k_prep_w1<<<(FHID * KPAD + 255) / 256, 256>>>(W1);

    // layer 1
    k_gemm1<<<(NNODES + 127) / 128, 256>>>(x);
    k_agg1 <<<(NNODES * 32 + 255) / 256, 256>>>(b1);

    // layer 2
    k_gemm2<<<(NNODES + 127) / 128, 256>>>(W2);
    k_agg2 <<<(NNODES * 32 + 255) / 256, 256>>>(b2, out);
}

// round 9
// speedup vs baseline: 2.1701x; 1.0010x over previous
#include <cuda_runtime.h>
#include <cuda_bf16.h>
#include <math.h>
#include <stdint.h>

#define NNODES 50000
#define NEDGES 800000
#define FIN    500
#define FHID   128
#define FOUT   47
#define F2S    48          // padded stride for layer-2 rows (16B-aligned)
#define KPAD   512         // padded K for W1 planes

// ---- scratch (static device globals; no allocation allowed) ----
__device__ float g_dinv[NNODES];
__device__ int   g_degi[NNODES];
__device__ int   g_off [NNODES + 1];
__device__ int   g_cur [NNODES];
__device__ int   g_csr [NEDGES];
__device__ float g_h1  [NNODES * FHID];   // (x@W1) * dinv[row]
__device__ float g_z1  [NNODES * FHID];
__device__ float g_h2  [NNODES * F2S];    // (z1@W2) * dinv[row], padded
__device__ __nv_bfloat16 g_w1hi[FHID * KPAD];   // n-major [128][512]
__device__ __nv_bfloat16 g_w1lo[FHID * KPAD];

// ---------------------------------------------------------------
// CSR build: count -> scan (+dinv) -> fill
// ---------------------------------------------------------------
__global__ void k_zero_deg() {
    int i = blockIdx.x * blockDim.x + threadIdx.x;
    if (i < NNODES) g_degi[i] = 0;
}
__global__ void k_count(const int* __restrict__ ei) {
    int e = blockIdx.x * blockDim.x + threadIdx.x;
    if (e < NEDGES) atomicAdd(&g_degi[ei[NEDGES + e]], 1);
}
__global__ __launch_bounds__(1024) void k_scan() {
    __shared__ int sdata[1024];
    const int t  = threadIdx.x;
    const int CH = (NNODES + 1023) / 1024;     // 49
    int lo = t * CH;
    int hi = lo + CH; if (hi > NNODES) hi = NNODES;
    int s = 0;
    for (int i = lo; i < hi; i++) s += g_degi[i];
    sdata[t] = s;
    __syncthreads();
    for (int o = 1; o < 1024; o <<= 1) {
        int v = (t >= o) ? sdata[t - o] : 0;
        __syncthreads();
        sdata[t] += v;
        __syncthreads();
    }
    int run = (t == 0) ? 0 : sdata[t - 1];
    for (int i = lo; i < hi; i++) {
        g_off[i] = run;
        g_cur[i] = run;
        g_dinv[i] = rsqrtf((float)(g_degi[i] + 1));   // +1 self-loop
        run += g_degi[i];
    }
    if (t == 1023) g_off[NNODES] = run;
}
__global__ void k_fill(const int* __restrict__ ei) {
    int e = blockIdx.x * blockDim.x + threadIdx.x;
    if (e >= NEDGES) return;
    int s = ei[e];
    int d = ei[NEDGES + e];
    int pos = atomicAdd(&g_cur[d], 1);
    g_csr[pos] = s;
}

// ---------------------------------------------------------------
// helpers
// ---------------------------------------------------------------
__device__ __forceinline__ uint32_t smem_u32(const void* p) {
    return (uint32_t)__cvta_generic_to_shared(p);
}
__device__ __forceinline__ uint32_t pack_bf2(__nv_bfloat16 a, __nv_bfloat16 b) {
    return (uint32_t)__bfloat16_as_ushort(a) | ((uint32_t)__bfloat16_as_ushort(b) << 16);
}

#define MMA_BF16(C, A, B)                                                     \
    asm volatile("mma.sync.aligned.m16n8k16.row.col.f32.bf16.bf16.f32 "       \
                 "{%0,%1,%2,%3}, {%4,%5,%6,%7}, {%8,%9}, {%0,%1,%2,%3};"      \
                 : "+f"((C)[0]), "+f"((C)[1]), "+f"((C)[2]), "+f"((C)[3])     \
                 : "r"((A)[0]), "r"((A)[1]), "r"((A)[2]), "r"((A)[3]),        \
                   "r"((B)[0]), "r"((B)[1]))

#define LDSM_X4(R, ADDR)                                                      \
    asm volatile("ldmatrix.sync.aligned.m8n8.x4.shared.b16 {%0,%1,%2,%3}, [%4];" \
                 : "=r"((R)[0]), "=r"((R)[1]), "=r"((R)[2]), "=r"((R)[3])     \
                 : "r"(ADDR))

#define LDSM_X2(R, ADDR)                                                      \
    asm volatile("ldmatrix.sync.aligned.m8n8.x2.shared.b16 {%0,%1}, [%2];"    \
                 : "=r"((R)[0]), "=r"((R)[1])                                 \
                 : "r"(ADDR))

// ---------------------------------------------------------------
// prep: W1 (500x128 f32, k-major) -> hi/lo bf16 planes, n-major [128][512]
// ---------------------------------------------------------------
__global__ void k_prep_w1(const float* __restrict__ W1) {
    int idx = blockIdx.x * blockDim.x + threadIdx.x;
    if (idx >= FHID * KPAD) return;
    int k = idx >> 7;        // 0..511 (coalesced read on W1 row)
    int n = idx & 127;
    float v = (k < FIN) ? W1[k * FHID + n] : 0.0f;
    __nv_bfloat16 h = __float2bfloat16_rn(v);
    __nv_bfloat16 l = __float2bfloat16_rn(v - __bfloat162float(h));
    g_w1hi[n * KPAD + k] = h;
    g_w1lo[n * KPAD + k] = l;
}

// ---------------------------------------------------------------
// GEMM1 (tensor cores, bf16 2-term split, fp32 accum, pipelined):
//   g_h1 = (x @ W1) * dinv[row]
// BM=128, BN=128, BK=32; 256 threads = 8 warps (4m x 2n)
// A: fp32 register-prefetch t+1 during compute of t; B: cp.async of
// precomputed bf16 planes.
// ---------------------------------------------------------------
#define SAS 40
#define SBS 40

__device__ __forceinline__ void loadA(const float* __restrict__ x, int row0,
                                      int tid, int k0, float4 v[4]) {
#pragma unroll
    for (int i = 0; i < 4; i++) {
        int fidx = tid + i * 256;
        int r  = fidx >> 3;
        int kq = fidx & 7;
        int gr = row0 + r;
        int gk = k0 + kq * 4;
        float4 t = make_float4(0.f, 0.f, 0.f, 0.f);
        if (gr < NNODES && gk + 3 < FIN)
            t = *(const float4*)(x + (size_t)gr * FIN + gk);
        v[i] = t;
    }
}

__global__ __launch_bounds__(256) void k_gemm1(const float* __restrict__ x) {
    __shared__ __nv_bfloat16 sAhi[128 * SAS];
    __shared__ __nv_bfloat16 sAlo[128 * SAS];
    __shared__ __nv_bfloat16 sBhi[128 * SBS];
    __shared__ __nv_bfloat16 sBlo[128 * SBS];

    const int tid  = threadIdx.x;
    const int lane = tid & 31;
    const int wid  = tid >> 5;
    const int wm   = wid >> 1;
    const int wn   = wid & 1;
    const int row0 = blockIdx.x * 128;

    float c[2][8][4];
#pragma unroll
    for (int mt = 0; mt < 2; mt++)
#pragma unroll
        for (int nt = 0; nt < 8; nt++)
#pragma unroll
            for (int j = 0; j < 4; j++) c[mt][nt][j] = 0.0f;

    float4 areg[4];
    loadA(x, row0, tid, 0, areg);

    for (int it = 0; it < 16; ++it) {
        const int k0 = it * 32;
        __syncthreads();          // previous compute done -> smem reusable

        // ---- store prefetched A (convert to hi/lo) ----
#pragma unroll
        for (int i = 0; i < 4; i++) {
            int fidx = tid + i * 256;
            int r  = fidx >> 3;
            int kq = fidx & 7;
            float4 v = areg[i];
            __nv_bfloat16 h0 = __float2bfloat16_rn(v.x);
            __nv_bfloat16 h1 = __float2bfloat16_rn(v.y);
            __nv_bfloat16 h2 = __float2bfloat16_rn(v.z);
            __nv_bfloat16 h3 = __float2bfloat16_rn(v.w);
            __nv_bfloat16 l0 = __float2bfloat16_rn(v.x - __bfloat162float(h0));
            __nv_bfloat16 l1 = __float2bfloat16_rn(v.y - __bfloat162float(h1));
            __nv_bfloat16 l2 = __float2bfloat16_rn(v.z - __bfloat162float(h2));
            __nv_bfloat16 l3 = __float2bfloat16_rn(v.w - __bfloat162float(h3));
            int base = r * SAS + kq * 4;
            *(uint32_t*)&sAhi[base]     = pack_bf2(h0, h1);
            *(uint32_t*)&sAhi[base + 2] = pack_bf2(h2, h3);
            *(uint32_t*)&sAlo[base]     = pack_bf2(l0, l1);
            *(uint32_t*)&sAlo[base + 2] = pack_bf2(l2, l3);
        }

        // ---- B tile via cp.async from precomputed planes ----
#pragma unroll
        for (int i = 0; i < 4; i++) {
            int fidx  = tid + i * 256;        // 0..1023
            int plane = fidx >> 9;            // 0=hi, 1=lo
            int rem   = fidx & 511;
            int n     = rem >> 2;
            int kq    = (rem & 3) * 8;        // 8 bf16 = 16B per copy
            const __nv_bfloat16* src =
                (plane ? g_w1lo : g_w1hi) + n * KPAD + k0 + kq;
            __nv_bfloat16* dst = (plane ? sBlo : sBhi) + n * SBS + kq;
            asm volatile("cp.async.cg.shared.global [%0], [%1], 16;"
                         :: "r"(smem_u32(dst)), "l"(src));
        }
        asm volatile("cp.async.commit_group;");

        // ---- prefetch next A tile into regs (overlaps with wait+compute) ----
        if (it + 1 < 16) loadA(x, row0, tid, (it + 1) * 32, areg);

        asm volatile("cp.async.wait_group 0;");
        __syncthreads();

        // ---- compute ----
#pragma unroll
        for (int kk = 0; kk < 32; kk += 16) {
            uint32_t ahi[2][4], alo[2][4];
#pragma unroll
            for (int mt = 0; mt < 2; mt++) {
                int r  = wm * 32 + mt * 16 + (lane & 15);
                int kc = kk + (lane >> 4) * 8;
                LDSM_X4(ahi[mt], smem_u32(&sAhi[r * SAS + kc]));
                LDSM_X4(alo[mt], smem_u32(&sAlo[r * SAS + kc]));
            }
#pragma unroll
            for (int nt = 0; nt < 8; nt++) {
                int bn = wn * 64 + nt * 8 + (lane & 7);
                int kc = kk + ((lane >> 3) & 1) * 8;
                uint32_t bh[2], bl[2];
                LDSM_X2(bh, smem_u32(&sBhi[bn * SBS + kc]));
                LDSM_X2(bl, smem_u32(&sBlo[bn * SBS + kc]));
#pragma unroll
                for (int mt = 0; mt < 2; mt++) {
                    MMA_BF16(c[mt][nt], ahi[mt], bh);   // hi*hi
                    MMA_BF16(c[mt][nt], ahi[mt], bl);   // hi*lo
                    MMA_BF16(c[mt][nt], alo[mt], bh);   // lo*hi
                }
            }
        }
    }

    // ---- epilogue: scale by dinv, write h1 ----
#pragma unroll
    for (int mt = 0; mt < 2; mt++) {
        int rA = row0 + wm * 32 + mt * 16 + (lane >> 2);
        int rB = rA + 8;
        float dA = (rA < NNODES) ? g_dinv[rA] : 0.f;
        float dB = (rB < NNODES) ? g_dinv[rB] : 0.f;
#pragma unroll
        for (int nt = 0; nt < 8; nt++) {
            int col = wn * 64 + nt * 8 + (lane & 3) * 2;
            if (rA < NNODES) {
                float2 v = make_float2(c[mt][nt][0] * dA, c[mt][nt][1] * dA);
                *(float2*)(g_h1 + (size_t)rA * FHID + col) = v;
            }
            if (rB < NNODES) {
                float2 v = make_float2(c[mt][nt][2] * dB, c[mt][nt][3] * dB);
                *(float2*)(g_h1 + (size_t)rB * FHID + col) = v;
            }
        }
    }
}

// ---------------------------------------------------------------
// agg1: one warp per dst node. acc = h1[dst] + sum_{src} h1[src];
//       z1 = relu(dinv*acc + b1). No atomics.
// ---------------------------------------------------------------
__global__ __launch_bounds__(256) void k_agg1(const float* __restrict__ b1) {
    int w    = (blockIdx.x * blockDim.x + threadIdx.x) >> 5;
    int lane = threadIdx.x & 31;
    if (w >= NNODES) return;
    const float4* base = (const float4*)g_h1;
    float4 acc = base[(size_t)w * 32 + lane];         // self-loop
    int p = g_off[w], e = g_off[w + 1];
    for (int p0 = p; p0 < e; p0 += 32) {
        int rem = e - p0;
        int s = (lane < rem) ? g_csr[p0 + lane] : 0;
        int cnt = rem < 32 ? rem : 32;
        for (int j = 0; j < cnt; j++) {
            int sj = __shfl_sync(0xFFFFFFFFu, s, j);
            float4 v = base[(size_t)sj * 32 + lane];
            acc.x += v.x; acc.y += v.y; acc.z += v.z; acc.w += v.w;
        }
    }
    float  d = g_dinv[w];
    float4 b = ((const float4*)b1)[lane];
    float4 z;
    z.x = fmaxf(fmaf(d, acc.x, b.x), 0.f);
    z.y = fmaxf(fmaf(d, acc.y, b.y), 0.f);
    z.z = fmaxf(fmaf(d, acc.z, b.z), 0.f);
    z.w = fmaxf(fmaf(d, acc.w, b.w), 0.f);
    ((float4*)g_z1)[(size_t)w * 32 + lane] = z;
}

// ---------------------------------------------------------------
// GEMM2: g_h2 = (z1 @ W2) * dinv[row]   (stride F2S=48, col 47 zero)
// ---------------------------------------------------------------
__global__ __launch_bounds__(256) void k_gemm2(const float* __restrict__ W2) {
    __shared__ float sA[16][128];
    __shared__ float sW[128][48];
    const int tid  = threadIdx.x;
    const int row0 = blockIdx.x * 128;
    const int tx   = tid & 15;
    const int ty   = tid >> 4;

    for (int idx = tid; idx < 128 * 48; idx += 256) {
        int k = idx / 48, n = idx % 48;
        sW[k][n] = (n < FOUT) ? W2[k * FOUT + n] : 0.0f;
    }

    float acc[8][3];
#pragma unroll
    for (int m = 0; m < 8; m++)
#pragma unroll
        for (int n = 0; n < 3; n++) acc[m][n] = 0.0f;

    const int arow  = tid >> 1;
    const int abase = (tid & 1) * 8;

    for (int k0 = 0; k0 < FHID; k0 += 16) {
        __syncthreads();
#pragma unroll
        for (int j = 0; j < 2; j++) {
            int c4 = abase + j * 4;
            float4 av = make_float4(0.f, 0.f, 0.f, 0.f);
            int gr = row0 + arow;
            if (gr < NNODES)
                av = *(const float4*)(g_z1 + (size_t)gr * FHID + k0 + c4);
            sA[c4 + 0][arow] = av.x;
            sA[c4 + 1][arow] = av.y;
            sA[c4 + 2][arow] = av.z;
            sA[c4 + 3][arow] = av.w;
        }
        __syncthreads();
#pragma unroll
        for (int k = 0; k < 16; k++) {
            float a[8];
            *(float4*)(a)     = *(const float4*)&sA[k][ty * 8];
            *(float4*)(a + 4) = *(const float4*)&sA[k][ty * 8 + 4];
            float b0 = sW[k0 + k][tx * 3 + 0];
            float b1 = sW[k0 + k][tx * 3 + 1];
            float b2 = sW[k0 + k][tx * 3 + 2];
#pragma unroll
            for (int m = 0; m < 8; m++) {
                acc[m][0] = fmaf(a[m], b0, acc[m][0]);
                acc[m][1] = fmaf(a[m], b1, acc[m][1]);
                acc[m][2] = fmaf(a[m], b2, acc[m][2]);
            }
        }
    }

#pragma unroll
    for (int m = 0; m < 8; m++) {
        int r = row0 + ty * 8 + m;
        if (r >= NNODES) continue;
        float d = g_dinv[r];
#pragma unroll
        for (int n = 0; n < 3; n++) {
            int cidx = tx * 3 + n;
            g_h2[(size_t)r * F2S + cidx] = acc[m][n] * d;
        }
    }
}

// ---------------------------------------------------------------
// agg2: one warp per dst. acc = h2[dst] + sum h2[src] (48 padded floats,
// lanes 0..11 hold float4 each); then fused bias + log_softmax -> out.
// ---------------------------------------------------------------
__global__ __launch_bounds__(256) void k_agg2(const float* __restrict__ b2,
                                              float* __restrict__ out) {
    int w    = (blockIdx.x * blockDim.x + threadIdx.x) >> 5;
    int lane = threadIdx.x & 31;
    if (w >= NNODES) return;
    const float4* base = (const float4*)g_h2;
    bool active = lane < 12;
    float4 acc = active ? base[(size_t)w * 12 + lane]
                        : make_float4(0.f, 0.f, 0.f, 0.f);
    int p = g_off[w], e = g_off[w + 1];
    for (int p0 = p; p0 < e; p0 += 32) {
        int rem = e - p0;
        int s = (lane < rem) ? g_csr[p0 + lane] : 0;
        int cnt = rem < 32 ? rem : 32;
        for (int j = 0; j < cnt; j++) {
            int sj = __shfl_sync(0xFFFFFFFFu, s, j);
            if (active) {
                float4 v = base[(size_t)sj * 12 + lane];
                acc.x += v.x; acc.y += v.y; acc.z += v.z; acc.w += v.w;
            }
        }
    }
    float d = g_dinv[w];
    float vv[4];
    float av[4] = {acc.x, acc.y, acc.z, acc.w};
    float m = -INFINITY;
#pragma unroll
    for (int j = 0; j < 4; j++) {
        int col = lane * 4 + j;
        vv[j] = (col < FOUT) ? fmaf(d, av[j], b2[col]) : -INFINITY;
        m = fmaxf(m, vv[j]);
    }
#pragma unroll
    for (int o = 16; o; o >>= 1) m = fmaxf(m, __shfl_xor_sync(0xFFFFFFFFu, m, o));
    float s = 0.f;
#pragma unroll
    for (int j = 0; j < 4; j++) {
        int col = lane * 4 + j;
        if (col < FOUT) s += expf(vv[j] - m);
    }
#pragma unroll
    for (int o = 16; o; o >>= 1) s += __shfl_xor_sync(0xFFFFFFFFu, s, o);
    float ls = m + logf(s);
#pragma unroll
    for (int j = 0; j < 4; j++) {
        int col = lane * 4 + j;
        if (col < FOUT) out[(size_t)w * FOUT + col] = vv[j] - ls;
    }
}

// ---------------------------------------------------------------
extern "C" void kernel_launch(void* const* d_in, const int* in_sizes, int n_in,
                              void* d_out, int out_size) {
    const float* x  = (const float*)d_in[0];
    const float* W1 = (const float*)d_in[1];
    const float* b1 = (const float*)d_in[2];
    const float* W2 = (const float*)d_in[3];
    const float* b2 = (const float*)d_in[4];
    const int*   ei = (const int*)d_in[5];     // int32 (JAX x64 disabled)
    float* out = (float*)d_out;

    (void)in_sizes; (void)n_in; (void)out_size;

    // CSR build + dinv
    k_zero_deg<<<(NNODES + 255) / 256, 256>>>();
    k_count   <<<(NEDGES + 255) / 256, 256>>>(ei);
    k_scan    <<<1, 1024>>>();
    k_fill    <<<(NEDGES + 255) / 256, 256>>>(ei);

    // W1 bf16 planes
    k_prep_w1<<<(FHID * KPAD + 255) / 256, 256>>>(W1);

    // layer 1
    k_gemm1<<<(NNODES + 127) / 128, 256>>>(x);
    k_agg1 <<<(NNODES * 32 + 255) / 256, 256>>>(b1);

    // layer 2
    k_gemm2<<<(NNODES + 127) / 128, 256>>>(W2);
    k_agg2 <<<(NNODES * 32 + 255) / 256, 256>>>(b2, out);
}